// round 4
// baseline (speedup 1.0000x reference)
#include <cuda_runtime.h>
#include <cuda_bf16.h>

// Z[b,o] = sum_i X[b,i] * W[i,o] * Werr[idx[b],i,o] + bias[o] * Berr[idx[b],o]
// B=256, IN=512, OUT=512, POOL=1000.
// HBM-stream bound (~256 MB gathered Werr). R3: KSPLIT=4 -> 512 blocks,
// 4096 warps (~28 warps/SM) to push DRAM from 70% toward ~85%.

constexpr int BDIM   = 256;
constexpr int IN     = 512;
constexpr int OUT    = 512;

constexpr int BLK_O   = 128;          // 32 lanes x float4
constexpr int BLK_B   = 2;            // batches per block
constexpr int KSPLIT  = 4;            // k-quarters per (batch, o-tile)
constexpr int KCH     = IN / KSPLIT;  // 128 iters per warp
constexpr int THREADS = BLK_B * KSPLIT * 32;  // 256

__global__ __launch_bounds__(THREADS, 2)
void aconnect_kernel(const float* __restrict__ X,
                     const float* __restrict__ W,
                     const float* __restrict__ bias,
                     const float* __restrict__ Werr,
                     const float* __restrict__ Berr,
                     const int*   __restrict__ idx,
                     float*       __restrict__ out)
{
    __shared__ float  xs[BLK_B][IN];
    __shared__ float4 red[THREADS / 32][32];

    const int tid  = threadIdx.x;
    const int lane = tid & 31;
    const int w    = tid >> 5;            // warp id in [0,8)
    const int bl   = w & (BLK_B - 1);     // batch-within-block (0..1)
    const int kq   = w >> 1;              // k-quarter (0..3)

    const int b0 = blockIdx.y * BLK_B;
    const int o0 = blockIdx.x * BLK_O;
    const int b  = b0 + bl;
    const int o  = o0 + lane * 4;

    // Hoist pool-index load so Werr base addr is ready before barrier release.
    const int p = idx[b];

    // Stage the 2 X rows (4 KB) into shared.
    #pragma unroll
    for (int k = tid; k < BLK_B * IN; k += THREADS) {
        const int rb = k >> 9;         // k / IN
        const int ci = k & (IN - 1);   // k % IN
        xs[rb][ci] = X[(size_t)(b0 + rb) * IN + ci];
    }
    __syncthreads();

    const float4* __restrict__ w4 =
        reinterpret_cast<const float4*>(W + (size_t)kq * KCH * OUT + o);
    const float4* __restrict__ e4 =
        reinterpret_cast<const float4*>(Werr + (size_t)p * IN * OUT
                                             + (size_t)kq * KCH * OUT + o);
    const float* __restrict__ xrow = &xs[bl][kq * KCH];

    float4 acc = make_float4(0.f, 0.f, 0.f, 0.f);

    // Per iter: one 16B W load (L1/L2 hit) + one 16B Werr load (DRAM stream).
    #pragma unroll 8
    for (int i = 0; i < KCH; ++i) {
        const float  x  = xrow[i];
        const float4 ww = w4[i * (OUT / 4)];
        const float4 ee = e4[i * (OUT / 4)];
        acc.x = fmaf(x * ww.x, ee.x, acc.x);
        acc.y = fmaf(x * ww.y, ee.y, acc.y);
        acc.z = fmaf(x * ww.z, ee.z, acc.z);
        acc.w = fmaf(x * ww.w, ee.w, acc.w);
    }

    // Cross-k-quarter reduction in shared: warps with same bl are
    // w = bl, bl+2, bl+4, bl+6; kq==0 warp accumulates the other three.
    red[w][lane] = acc;
    __syncthreads();

    if (kq == 0) {
        #pragma unroll
        for (int q = 1; q < KSPLIT; ++q) {
            const float4 other = red[w + q * BLK_B][lane];
            acc.x += other.x;  acc.y += other.y;
            acc.z += other.z;  acc.w += other.w;
        }

        // Noisy bias epilogue.
        const float4 bi = *reinterpret_cast<const float4*>(bias + o);
        const float4 be = *reinterpret_cast<const float4*>(Berr + (size_t)p * OUT + o);
        acc.x = fmaf(bi.x, be.x, acc.x);
        acc.y = fmaf(bi.y, be.y, acc.y);
        acc.z = fmaf(bi.z, be.z, acc.z);
        acc.w = fmaf(bi.w, be.w, acc.w);

        *reinterpret_cast<float4*>(out + (size_t)b * OUT + o) = acc;
    }
}

extern "C" void kernel_launch(void* const* d_in, const int* in_sizes, int n_in,
                              void* d_out, int out_size)
{
    const float* X    = (const float*)d_in[0];  // [256, 512]
    const float* W    = (const float*)d_in[1];  // [512, 512]
    const float* bias = (const float*)d_in[2];  // [512]
    const float* Werr = (const float*)d_in[3];  // [1000, 512, 512]
    const float* Berr = (const float*)d_in[4];  // [1000, 512]
    const int*   idx  = (const int*)  d_in[5];  // [256]
    float*       out  = (float*)d_out;          // [256, 512]

    dim3 grid(OUT / BLK_O, BDIM / BLK_B);       // (4, 128) = 512 blocks
    aconnect_kernel<<<grid, THREADS>>>(X, W, bias, Werr, Berr, idx, out);
}

// round 6
// speedup vs baseline: 1.0553x; 1.0553x over previous
#include <cuda_runtime.h>
#include <cuda_bf16.h>

// Z[b,o] = sum_i X[b,i] * W[i,o] * Werr[idx[b],i,o] + bias[o] * Berr[idx[b],o]
// B=256, IN=512, OUT=512, POOL=1000.
// HBM-stream bound (~256 MB gathered Werr). R4 lesson: 96 regs capped
// residency at 2 blocks/SM regardless of grid. Force 64 regs via
// __launch_bounds__(256,4) + unroll 4 -> 4 blocks/SM, 512 blocks = 1 wave.

constexpr int BDIM   = 256;
constexpr int IN     = 512;
constexpr int OUT    = 512;

constexpr int BLK_O   = 128;          // 32 lanes x float4
constexpr int BLK_B   = 2;            // batches per block
constexpr int KSPLIT  = 4;            // k-quarters per (batch, o-tile)
constexpr int KCH     = IN / KSPLIT;  // 128 iters per warp
constexpr int THREADS = BLK_B * KSPLIT * 32;  // 256

__global__ __launch_bounds__(THREADS, 4)
void aconnect_kernel(const float* __restrict__ X,
                     const float* __restrict__ W,
                     const float* __restrict__ bias,
                     const float* __restrict__ Werr,
                     const float* __restrict__ Berr,
                     const int*   __restrict__ idx,
                     float*       __restrict__ out)
{
    __shared__ float  xs[BLK_B][IN];
    __shared__ float4 red[THREADS / 32][32];

    const int tid  = threadIdx.x;
    const int lane = tid & 31;
    const int w    = tid >> 5;            // warp id in [0,8)
    const int bl   = w & (BLK_B - 1);     // batch-within-block (0..1)
    const int kq   = w >> 1;              // k-quarter (0..3)

    const int b0 = blockIdx.y * BLK_B;
    const int o0 = blockIdx.x * BLK_O;
    const int b  = b0 + bl;
    const int o  = o0 + lane * 4;

    // Hoist pool-index load so Werr base addr is ready before barrier release.
    const int p = idx[b];

    // Stage the 2 X rows (4 KB) into shared.
    #pragma unroll
    for (int k = tid; k < BLK_B * IN; k += THREADS) {
        const int rb = k >> 9;         // k / IN
        const int ci = k & (IN - 1);   // k % IN
        xs[rb][ci] = X[(size_t)(b0 + rb) * IN + ci];
    }
    __syncthreads();

    const float4* __restrict__ w4 =
        reinterpret_cast<const float4*>(W + (size_t)kq * KCH * OUT + o);
    const float4* __restrict__ e4 =
        reinterpret_cast<const float4*>(Werr + (size_t)p * IN * OUT
                                             + (size_t)kq * KCH * OUT + o);
    const float* __restrict__ xrow = &xs[bl][kq * KCH];

    float4 acc = make_float4(0.f, 0.f, 0.f, 0.f);

    // Per iter: one 16B W load (L1/L2 hit) + one 16B Werr load (DRAM stream).
    // Unroll 4 keeps live load regs ~32 so total stays within the 64-reg cap.
    #pragma unroll 4
    for (int i = 0; i < KCH; ++i) {
        const float  x  = xrow[i];
        const float4 ww = w4[i * (OUT / 4)];
        const float4 ee = e4[i * (OUT / 4)];
        acc.x = fmaf(x * ww.x, ee.x, acc.x);
        acc.y = fmaf(x * ww.y, ee.y, acc.y);
        acc.z = fmaf(x * ww.z, ee.z, acc.z);
        acc.w = fmaf(x * ww.w, ee.w, acc.w);
    }

    // Cross-k-quarter reduction in shared: warps with same bl are
    // w = bl, bl+2, bl+4, bl+6; kq==0 warp accumulates the other three.
    red[w][lane] = acc;
    __syncthreads();

    if (kq == 0) {
        #pragma unroll
        for (int q = 1; q < KSPLIT; ++q) {
            const float4 other = red[w + q * BLK_B][lane];
            acc.x += other.x;  acc.y += other.y;
            acc.z += other.z;  acc.w += other.w;
        }

        // Noisy bias epilogue.
        const float4 bi = *reinterpret_cast<const float4*>(bias + o);
        const float4 be = *reinterpret_cast<const float4*>(Berr + (size_t)p * OUT + o);
        acc.x = fmaf(bi.x, be.x, acc.x);
        acc.y = fmaf(bi.y, be.y, acc.y);
        acc.z = fmaf(bi.z, be.z, acc.z);
        acc.w = fmaf(bi.w, be.w, acc.w);

        *reinterpret_cast<float4*>(out + (size_t)b * OUT + o) = acc;
    }
}

extern "C" void kernel_launch(void* const* d_in, const int* in_sizes, int n_in,
                              void* d_out, int out_size)
{
    const float* X    = (const float*)d_in[0];  // [256, 512]
    const float* W    = (const float*)d_in[1];  // [512, 512]
    const float* bias = (const float*)d_in[2];  // [512]
    const float* Werr = (const float*)d_in[3];  // [1000, 512, 512]
    const float* Berr = (const float*)d_in[4];  // [1000, 512]
    const int*   idx  = (const int*)  d_in[5];  // [256]
    float*       out  = (float*)d_out;          // [256, 512]

    dim3 grid(OUT / BLK_O, BDIM / BLK_B);       // (4, 128) = 512 blocks
    aconnect_kernel<<<grid, THREADS>>>(X, W, bias, Werr, Berr, idx, out);
}